// round 6
// baseline (speedup 1.0000x reference)
#include <cuda_runtime.h>
#include <cuda_bf16.h>

#define SEQ_DIM 256
#define PAIR_DIM 128
#define HID 32
#define LTOK 384
#define EPS 1e-5f

// Scratch (static device memory; no allocation)
__device__ float g_s1t[HID * LTOK];          // s1 transposed: [d][i]
__device__ float g_s2[LTOK * HID];           // s2: [j][f]
__device__ float g_T[LTOK * HID * PAIR_DIM]; // T[j][d*128+p]

// ---------------------------------------------------------------------------
// Kernel A: LayerNorm + two projections. One block per token, 256 threads.
// ---------------------------------------------------------------------------
__global__ void ln_proj_kernel(const float* __restrict__ seq,
                               const float* __restrict__ gamma,
                               const float* __restrict__ beta,
                               const float* __restrict__ w1,
                               const float* __restrict__ b1,
                               const float* __restrict__ w2,
                               const float* __restrict__ b2)
{
    const int i = blockIdx.x;
    const int tid = threadIdx.x;
    const int lane = tid & 31;
    const int wid = tid >> 5;

    __shared__ float xs[SEQ_DIM];
    __shared__ float red[8];
    __shared__ float s_mu, s_var;

    float v = seq[i * SEQ_DIM + tid];

    // mean
    float s = v;
    #pragma unroll
    for (int o = 16; o > 0; o >>= 1) s += __shfl_down_sync(0xffffffffu, s, o);
    if (lane == 0) red[wid] = s;
    __syncthreads();
    if (tid == 0) {
        float t = 0.f;
        #pragma unroll
        for (int k = 0; k < 8; k++) t += red[k];
        s_mu = t * (1.0f / SEQ_DIM);
    }
    __syncthreads();
    const float mu = s_mu;
    const float dc = v - mu;

    // variance
    __syncthreads();
    float s2 = dc * dc;
    #pragma unroll
    for (int o = 16; o > 0; o >>= 1) s2 += __shfl_down_sync(0xffffffffu, s2, o);
    if (lane == 0) red[wid] = s2;
    __syncthreads();
    if (tid == 0) {
        float t = 0.f;
        #pragma unroll
        for (int k = 0; k < 8; k++) t += red[k];
        s_var = t * (1.0f / SEQ_DIM);
    }
    __syncthreads();

    const float inv = rsqrtf(s_var + EPS);
    xs[tid] = dc * inv * gamma[tid] + beta[tid];
    __syncthreads();

    // 64 dot products (32 for s1, 32 for s2), 8 per warp
    for (int o = wid; o < 64; o += 8) {
        const bool is1 = (o < 32);
        const int h = is1 ? o : (o - 32);
        const float* wr = (is1 ? w1 : w2) + h * SEQ_DIM;
        float acc = 0.f;
        #pragma unroll
        for (int k = lane; k < SEQ_DIM; k += 32) acc += xs[k] * wr[k];
        #pragma unroll
        for (int off = 16; off > 0; off >>= 1)
            acc += __shfl_down_sync(0xffffffffu, acc, off);
        if (lane == 0) {
            if (is1) g_s1t[h * LTOK + i] = acc + b1[h];
            else     g_s2[i * HID + h]  = acc + b2[h];
        }
    }
}

// ---------------------------------------------------------------------------
// Kernel B: T[j][d*128+p] = sum_f s2[j][f] * w3[p*1024 + d*32 + f]
// Block handles JT=8 consecutive j and a quarter of the 4096 (d,p) space.
// ---------------------------------------------------------------------------
#define JT 8
__global__ void expand_t_kernel(const float* __restrict__ w3)
{
    const int jb = blockIdx.x;   // 0..47
    const int nq = blockIdx.y;   // 0..3
    const int tid = threadIdx.x; // 256

    __shared__ float s2s[JT][HID];
    {
        const int jj = tid >> 5, f = tid & 31;
        s2s[jj][f] = g_s2[(jb * JT + jj) * HID + f];
    }
    __syncthreads();

    float acc[4][JT];
    #pragma unroll
    for (int nn = 0; nn < 4; nn++)
        #pragma unroll
        for (int jj = 0; jj < JT; jj++) acc[nn][jj] = 0.f;

    #pragma unroll
    for (int nn = 0; nn < 4; nn++) {
        const int np = nq * 1024 + nn * 256 + tid;
        const int d = np >> 7, p = np & 127;
        const float4* wp = (const float4*)(w3 + p * (HID * HID) + d * HID);
        #pragma unroll
        for (int q = 0; q < 8; q++) {
            const float4 w4 = wp[q];
            const int f = q * 4;
            #pragma unroll
            for (int jj = 0; jj < JT; jj++) {
                float a = acc[nn][jj];
                a += w4.x * s2s[jj][f + 0];
                a += w4.y * s2s[jj][f + 1];
                a += w4.z * s2s[jj][f + 2];
                a += w4.w * s2s[jj][f + 3];
                acc[nn][jj] = a;
            }
        }
    }

    #pragma unroll
    for (int jj = 0; jj < JT; jj++) {
        const int j = jb * JT + jj;
        #pragma unroll
        for (int nn = 0; nn < 4; nn++) {
            const int np = nq * 1024 + nn * 256 + tid;
            g_T[j * 4096 + np] = acc[nn][jj];
        }
    }
}

// ---------------------------------------------------------------------------
// Kernel C: pair[i,j,p] = b3[p] + sum_d s1[i,d] * T[j][d*128+p]
// grid (3 i-tiles, 384 j). 128x128 output tile, K=32 (single smem fill).
// ---------------------------------------------------------------------------
__global__ void __launch_bounds__(256, 2)
pair_gemm_kernel(const float* __restrict__ b3, float* __restrict__ out)
{
    __shared__ float As[HID * 128];  // As[d][i_local]
    __shared__ float Bs[HID * 128];  // Bs[d][p]

    const int ib = blockIdx.x;  // 0..2
    const int j  = blockIdx.y;  // 0..383
    const int tid = threadIdx.x;
    const int tx = tid & 15;    // p direction
    const int ty = tid >> 4;    // i direction

    // Fill smem: 1024 float4 each, 4 per thread
    {
        float4* sa = (float4*)As;
        float4* sb = (float4*)Bs;
        const float4* gb = (const float4*)(g_T + j * 4096);
        const float4* ga = (const float4*)g_s1t;
        #pragma unroll
        for (int k = 0; k < 4; k++) {
            const int f4 = k * 256 + tid;
            const int d = f4 >> 5, rem = f4 & 31;
            sa[f4] = ga[d * (LTOK / 4) + ib * 32 + rem];
            sb[f4] = gb[f4];
        }
    }
    __syncthreads();

    float acc[8][8];
    {
        float bv[8];
        *(float4*)&bv[0] = *(const float4*)&b3[tx * 8];
        *(float4*)&bv[4] = *(const float4*)&b3[tx * 8 + 4];
        #pragma unroll
        for (int u = 0; u < 8; u++)
            #pragma unroll
            for (int v = 0; v < 8; v++) acc[u][v] = bv[v];
    }

    #pragma unroll 8
    for (int d = 0; d < HID; d++) {
        float a[8], b[8];
        *(float4*)&a[0] = *(const float4*)&As[d * 128 + ty * 8];
        *(float4*)&a[4] = *(const float4*)&As[d * 128 + ty * 8 + 4];
        *(float4*)&b[0] = *(const float4*)&Bs[d * 128 + tx * 8];
        *(float4*)&b[4] = *(const float4*)&Bs[d * 128 + tx * 8 + 4];
        #pragma unroll
        for (int u = 0; u < 8; u++)
            #pragma unroll
            for (int v = 0; v < 8; v++)
                acc[u][v] += a[u] * b[v];
    }

    #pragma unroll
    for (int u = 0; u < 8; u++) {
        const int i = ib * 128 + ty * 8 + u;
        float* op = out + ((size_t)i * LTOK + j) * PAIR_DIM + tx * 8;
        *(float4*)op       = *(float4*)&acc[u][0];
        *(float4*)(op + 4) = *(float4*)&acc[u][4];
    }
}

// ---------------------------------------------------------------------------
extern "C" void kernel_launch(void* const* d_in, const int* in_sizes, int n_in,
                              void* d_out, int out_size)
{
    const float* seq   = (const float*)d_in[0];
    const float* gamma = (const float*)d_in[1];
    const float* beta  = (const float*)d_in[2];
    const float* w1    = (const float*)d_in[3];
    const float* b1    = (const float*)d_in[4];
    const float* w2    = (const float*)d_in[5];
    const float* b2    = (const float*)d_in[6];
    const float* w3    = (const float*)d_in[7];
    const float* b3    = (const float*)d_in[8];
    float* out = (float*)d_out;

    ln_proj_kernel<<<LTOK, 256>>>(seq, gamma, beta, w1, b1, w2, b2);
    expand_t_kernel<<<dim3(LTOK / JT, 4), 256>>>(w3);
    pair_gemm_kernel<<<dim3(3, LTOK), 256>>>(b3, out);
}

// round 9
// speedup vs baseline: 1.0925x; 1.0925x over previous
#include <cuda_runtime.h>
#include <cuda_bf16.h>
#include <cstdint>

#define SEQ_DIM 256
#define PAIR_DIM 128
#define HID 32
#define LTOK 384
#define EPS 1e-5f

// Scratch (static device memory; no allocation)
// s1 split: [i][64] bf16, cols 0-31 = hi, 32-63 = lo
__device__ __nv_bfloat16 g_s1b[LTOK * 64];
// s2: [j][f] fp32
__device__ float g_s2[LTOK * HID];
// T split: [j][p][64] bf16, cols 0-31 = hi(d), 32-63 = lo(d)
__device__ __nv_bfloat16 g_Tb[LTOK * PAIR_DIM * 64];

// ---------------------------------------------------------------------------
__device__ __forceinline__ uint32_t smem_to_u32(const void* p) {
    uint32_t a;
    asm("{ .reg .u64 t; cvta.to.shared.u64 t, %1; cvt.u32.u64 %0, t; }"
        : "=r"(a) : "l"(p));
    return a;
}

#define LDSM_X4(r, addr) \
    asm volatile("ldmatrix.sync.aligned.m8n8.x4.shared.b16 {%0,%1,%2,%3}, [%4];" \
        : "=r"((r)[0]), "=r"((r)[1]), "=r"((r)[2]), "=r"((r)[3]) : "r"(addr))

#define MMA16816(c, a, b0, b1) \
    asm volatile("mma.sync.aligned.m16n8k16.row.col.f32.bf16.bf16.f32 " \
        "{%0,%1,%2,%3}, {%4,%5,%6,%7}, {%8,%9}, {%0,%1,%2,%3};" \
        : "+f"((c)[0]), "+f"((c)[1]), "+f"((c)[2]), "+f"((c)[3]) \
        : "r"((a)[0]), "r"((a)[1]), "r"((a)[2]), "r"((a)[3]), "r"(b0), "r"(b1))

// ---------------------------------------------------------------------------
// Kernel A: LayerNorm + both projections. Warp-per-token, 4 tokens/block.
// ---------------------------------------------------------------------------
__device__ __forceinline__ float wredsum(float v) {
    #pragma unroll
    for (int o = 16; o > 0; o >>= 1) v += __shfl_xor_sync(0xffffffffu, v, o);
    return v;
}

__global__ void __launch_bounds__(128) ln_proj_kernel(
    const float* __restrict__ seq,
    const float* __restrict__ gamma,
    const float* __restrict__ beta,
    const float* __restrict__ w1,
    const float* __restrict__ b1,
    const float* __restrict__ w2,
    const float* __restrict__ b2)
{
    const int wid = threadIdx.x >> 5;
    const int lane = threadIdx.x & 31;
    const int i = blockIdx.x * 4 + wid;   // token

    const float4* sp = (const float4*)(seq + i * SEQ_DIM + lane * 8);
    float4 xa = sp[0], xb = sp[1];
    float x[8] = {xa.x, xa.y, xa.z, xa.w, xb.x, xb.y, xb.z, xb.w};

    float s = 0.f;
    #pragma unroll
    for (int q = 0; q < 8; q++) s += x[q];
    const float mu = wredsum(s) * (1.0f / SEQ_DIM);

    float ss = 0.f;
    #pragma unroll
    for (int q = 0; q < 8; q++) { x[q] -= mu; ss += x[q] * x[q]; }
    const float inv = rsqrtf(wredsum(ss) * (1.0f / SEQ_DIM) + EPS);

    const float4* gp = (const float4*)(gamma + lane * 8);
    const float4* bp = (const float4*)(beta + lane * 8);
    float4 ga = gp[0], gb = gp[1], ba = bp[0], bb = bp[1];
    float g[8] = {ga.x, ga.y, ga.z, ga.w, gb.x, gb.y, gb.z, gb.w};
    float be[8] = {ba.x, ba.y, ba.z, ba.w, bb.x, bb.y, bb.z, bb.w};
    float xn[8];
    #pragma unroll
    for (int q = 0; q < 8; q++) xn[q] = x[q] * inv * g[q] + be[q];

    float rs1 = 0.f, rs2 = 0.f;
    #pragma unroll
    for (int h0 = 0; h0 < 32; h0 += 4) {
        float a[4];
        #pragma unroll
        for (int u = 0; u < 4; u++) {
            const float4* wp = (const float4*)(w1 + (h0 + u) * SEQ_DIM + lane * 8);
            float4 wa = wp[0], wb = wp[1];
            a[u] = xn[0]*wa.x + xn[1]*wa.y + xn[2]*wa.z + xn[3]*wa.w
                 + xn[4]*wb.x + xn[5]*wb.y + xn[6]*wb.z + xn[7]*wb.w;
        }
        #pragma unroll
        for (int u = 0; u < 4; u++) {
            float r = wredsum(a[u]);
            if (lane == h0 + u) rs1 = r;
        }
    }
    #pragma unroll
    for (int h0 = 0; h0 < 32; h0 += 4) {
        float a[4];
        #pragma unroll
        for (int u = 0; u < 4; u++) {
            const float4* wp = (const float4*)(w2 + (h0 + u) * SEQ_DIM + lane * 8);
            float4 wa = wp[0], wb = wp[1];
            a[u] = xn[0]*wa.x + xn[1]*wa.y + xn[2]*wa.z + xn[3]*wa.w
                 + xn[4]*wb.x + xn[5]*wb.y + xn[6]*wb.z + xn[7]*wb.w;
        }
        #pragma unroll
        for (int u = 0; u < 4; u++) {
            float r = wredsum(a[u]);
            if (lane == h0 + u) rs2 = r;
        }
    }

    const float s1v = rs1 + b1[lane];
    const __nv_bfloat16 hi = __float2bfloat16(s1v);
    const float lov = s1v - __bfloat162float(hi);
    g_s1b[i * 64 + lane]      = hi;
    g_s1b[i * 64 + 32 + lane] = __float2bfloat16(lov);
    g_s2[i * HID + lane] = rs2 + b2[lane];
}

// ---------------------------------------------------------------------------
// Kernel B: T[j][p][d] = sum_f s2[j][f] * w3[p*1024 + d*32 + f]
// written as bf16 hi/lo into g_Tb[j][p*64 + d] / [.. + 32 + d].
// ---------------------------------------------------------------------------
#define JT 8
__global__ void expand_t_kernel(const float* __restrict__ w3)
{
    const int jb = blockIdx.x;   // 0..47
    const int nq = blockIdx.y;   // 0..3
    const int tid = threadIdx.x; // 256

    __shared__ float s2s[JT][HID];
    s2s[tid >> 5][tid & 31] = g_s2[(jb * JT + (tid >> 5)) * HID + (tid & 31)];
    __syncthreads();

    float acc[4][JT];
    #pragma unroll
    for (int nn = 0; nn < 4; nn++)
        #pragma unroll
        for (int jj = 0; jj < JT; jj++) acc[nn][jj] = 0.f;

    #pragma unroll
    for (int nn = 0; nn < 4; nn++) {
        const int idx = nq * 1024 + nn * 256 + tid;
        const int d = idx & 31, p = idx >> 5;
        const float4* wp = (const float4*)(w3 + p * (HID * HID) + d * HID);
        #pragma unroll
        for (int q = 0; q < 8; q++) {
            const float4 w4 = wp[q];
            const int f = q * 4;
            #pragma unroll
            for (int jj = 0; jj < JT; jj++) {
                float a = acc[nn][jj];
                a += w4.x * s2s[jj][f + 0];
                a += w4.y * s2s[jj][f + 1];
                a += w4.z * s2s[jj][f + 2];
                a += w4.w * s2s[jj][f + 3];
                acc[nn][jj] = a;
            }
        }
    }

    #pragma unroll
    for (int jj = 0; jj < JT; jj++) {
        const int j = jb * JT + jj;
        #pragma unroll
        for (int nn = 0; nn < 4; nn++) {
            const int idx = nq * 1024 + nn * 256 + tid;
            const int d = idx & 31, p = idx >> 5;
            const float v = acc[nn][jj];
            const __nv_bfloat16 hi = __float2bfloat16(v);
            g_Tb[j * 8192 + p * 64 + d]      = hi;
            g_Tb[j * 8192 + p * 64 + 32 + d] = __float2bfloat16(v - __bfloat162float(hi));
        }
    }
}

// ---------------------------------------------------------------------------
// Kernel C: pair GEMM via mma.sync bf16 (hi/lo split, lo*lo dropped).
// Tile M=128 (i), N=128 (p) per (ib, j). 8 warps: 2x4, each 64x32.
// Smem rows padded to 72 bf16 (144B) -> conflict-free ldmatrix.
// ---------------------------------------------------------------------------
__global__ void __launch_bounds__(256) pair_mma_kernel(
    const float* __restrict__ b3, float* __restrict__ out)
{
    __shared__ __align__(16) __nv_bfloat16 As[128 * 72];
    __shared__ __align__(16) __nv_bfloat16 Bs[128 * 72];

    const int tid = threadIdx.x;
    const int wid = tid >> 5, lane = tid & 31;
    const int ib = blockIdx.x;  // 0..2
    const int j  = blockIdx.y;  // 0..383
    const int warp_m = wid >> 2;   // 0..1
    const int warp_n = wid & 3;    // 0..3

    // Fill smem tiles: 1024 x 16B each, coalesced.
    const uint4* ga = (const uint4*)(g_s1b + ib * 128 * 64);
    const uint4* gb = (const uint4*)(g_Tb + (size_t)j * 8192);
    #pragma unroll
    for (int q = 0; q < 4; q++) {
        const int idx = q * 256 + tid;          // 0..1023
        const int row = idx >> 3, c = idx & 7;  // 8x16B per 64-col row
        *(uint4*)(As + row * 72 + c * 8) = ga[idx];
        *(uint4*)(Bs + row * 72 + c * 8) = gb[idx];
    }
    __syncthreads();

    const uint32_t aBase = smem_to_u32(As);
    const uint32_t bBase = smem_to_u32(Bs);

    // ldmatrix lane addressing
    const int arow = warp_m * 64 + (lane & 15);
    const int acol = (lane >> 4) * 8;
    const uint32_t aAddr0 = aBase + (uint32_t)arow * 144 + (uint32_t)acol * 2;
    const int brow = warp_n * 32 + ((lane >> 4) & 1) * 8 + (lane & 7);
    const int bcol = ((lane >> 3) & 1) * 8;
    const uint32_t bAddr0 = bBase + (uint32_t)brow * 144 + (uint32_t)bcol * 2;

    // Accumulators init with bias
    float acc[4][4][4];
    const int pc = warp_n * 32 + 2 * (lane & 3);
    #pragma unroll
    for (int nt = 0; nt < 4; nt++) {
        const float bv0 = b3[pc + nt * 8];
        const float bv1 = b3[pc + nt * 8 + 1];
        #pragma unroll
        for (int mt = 0; mt < 4; mt++) {
            acc[mt][nt][0] = bv0; acc[mt][nt][1] = bv1;
            acc[mt][nt][2] = bv0; acc[mt][nt][3] = bv1;
        }
    }

    // 6 k16 steps: hi*hi (k 0,16), hi*lo (A 0,16 x B 32,48), lo*hi (A 32,48 x B 0,16)
    const int ka[6] = {0, 16, 0, 16, 32, 48};
    const int kb[6] = {0, 16, 32, 48, 0, 16};

    #pragma unroll
    for (int s = 0; s < 6; s++) {
        uint32_t af[4][4], bf[2][4];
        #pragma unroll
        for (int mt = 0; mt < 4; mt++)
            LDSM_X4(af[mt], aAddr0 + (uint32_t)(mt * 16 * 144 + ka[s] * 2));
        #pragma unroll
        for (int np = 0; np < 2; np++)
            LDSM_X4(bf[np], bAddr0 + (uint32_t)(np * 16 * 144 + kb[s] * 2));
        #pragma unroll
        for (int mt = 0; mt < 4; mt++)
            #pragma unroll
            for (int nt = 0; nt < 4; nt++)
                MMA16816(acc[mt][nt], af[mt],
                         bf[nt >> 1][(nt & 1) * 2], bf[nt >> 1][(nt & 1) * 2 + 1]);
    }

    // Epilogue: direct stores (bias already folded in)
    const int r0 = ib * 128 + warp_m * 64 + (lane >> 2);
    #pragma unroll
    for (int mt = 0; mt < 4; mt++) {
        const int i0 = r0 + mt * 16;
        float* p0 = out + ((size_t)i0 * LTOK + j) * PAIR_DIM + pc;
        float* p1 = p0 + (size_t)8 * LTOK * PAIR_DIM;
        #pragma unroll
        for (int nt = 0; nt < 4; nt++) {
            *(float2*)(p0 + nt * 8) = make_float2(acc[mt][nt][0], acc[mt][nt][1]);
            *(float2*)(p1 + nt * 8) = make_float2(acc[mt][nt][2], acc[mt][nt][3]);
        }
    }
}

// ---------------------------------------------------------------------------
extern "C" void kernel_launch(void* const* d_in, const int* in_sizes, int n_in,
                              void* d_out, int out_size)
{
    const float* seq   = (const float*)d_in[0];
    const float* gamma = (const float*)d_in[1];
    const float* beta  = (const float*)d_in[2];
    const float* w1    = (const float*)d_in[3];
    const float* b1    = (const float*)d_in[4];
    const float* w2    = (const float*)d_in[5];
    const float* b2    = (const float*)d_in[6];
    const float* w3    = (const float*)d_in[7];
    const float* b3    = (const float*)d_in[8];
    float* out = (float*)d_out;

    ln_proj_kernel<<<LTOK / 4, 128>>>(seq, gamma, beta, w1, b1, w2, b2);
    expand_t_kernel<<<dim3(LTOK / JT, 4), 256>>>(w3);
    pair_mma_kernel<<<dim3(3, LTOK), 256>>>(b3, out);
}

// round 10
// speedup vs baseline: 1.3297x; 1.2171x over previous
#include <cuda_runtime.h>
#include <cuda_bf16.h>
#include <cstdint>

#define SEQ_DIM 256
#define PAIR_DIM 128
#define HID 32
#define LTOK 384
#define EPS 1e-5f

// Scratch (static device memory; no allocation)
// s1 split: [i][64] bf16, cols 0-31 = hi, 32-63 = lo
__device__ __nv_bfloat16 g_s1b[LTOK * 64];
// s2: [j][f] fp32
__device__ float g_s2[LTOK * HID];
// T split: [j][p][64] bf16, cols 0-31 = hi(d), 32-63 = lo(d)
__device__ __nv_bfloat16 g_Tb[LTOK * PAIR_DIM * 64];

// ---------------------------------------------------------------------------
__device__ __forceinline__ uint32_t smem_to_u32(const void* p) {
    uint32_t a;
    asm("{ .reg .u64 t; cvta.to.shared.u64 t, %1; cvt.u32.u64 %0, t; }"
        : "=r"(a) : "l"(p));
    return a;
}

#define LDSM_X4(r, addr) \
    asm volatile("ldmatrix.sync.aligned.m8n8.x4.shared.b16 {%0,%1,%2,%3}, [%4];" \
        : "=r"((r)[0]), "=r"((r)[1]), "=r"((r)[2]), "=r"((r)[3]) : "r"(addr))

#define MMA16816(c, a, b0, b1) \
    asm volatile("mma.sync.aligned.m16n8k16.row.col.f32.bf16.bf16.f32 " \
        "{%0,%1,%2,%3}, {%4,%5,%6,%7}, {%8,%9}, {%0,%1,%2,%3};" \
        : "+f"((c)[0]), "+f"((c)[1]), "+f"((c)[2]), "+f"((c)[3]) \
        : "r"((a)[0]), "r"((a)[1]), "r"((a)[2]), "r"((a)[3]), "r"(b0), "r"(b1))

// ---------------------------------------------------------------------------
// Kernel A: LayerNorm + both projections. Block-per-token, 256 threads.
// Single-pass stats (sum, sumsq); dot phase = quarter-dots + smem combine
// (no shfl in the dot phase; 16-deep load MLP per thread).
// ---------------------------------------------------------------------------
__global__ void __launch_bounds__(256) ln_proj_kernel(
    const float* __restrict__ seq,
    const float* __restrict__ gamma,
    const float* __restrict__ beta,
    const float* __restrict__ w1,
    const float* __restrict__ b1,
    const float* __restrict__ w2,
    const float* __restrict__ b2)
{
    const int i = blockIdx.x;
    const int tid = threadIdx.x;
    const int lane = tid & 31;
    const int wid = tid >> 5;

    __shared__ float xs[SEQ_DIM];
    __shared__ float2 red[8];
    __shared__ float s_mu, s_inv;
    __shared__ float part[4][64];

    const float v = seq[i * SEQ_DIM + tid];

    // one-pass sum + sumsq
    float s = v, q = v * v;
    #pragma unroll
    for (int o = 16; o > 0; o >>= 1) {
        s += __shfl_xor_sync(0xffffffffu, s, o);
        q += __shfl_xor_sync(0xffffffffu, q, o);
    }
    if (lane == 0) red[wid] = make_float2(s, q);
    __syncthreads();
    if (wid == 0) {
        float2 r = (lane < 8) ? red[lane] : make_float2(0.f, 0.f);
        #pragma unroll
        for (int o = 4; o > 0; o >>= 1) {
            r.x += __shfl_xor_sync(0xffffffffu, r.x, o);
            r.y += __shfl_xor_sync(0xffffffffu, r.y, o);
        }
        if (lane == 0) {
            const float mu = r.x * (1.0f / SEQ_DIM);
            const float var = r.y * (1.0f / SEQ_DIM) - mu * mu;
            s_mu = mu;
            s_inv = rsqrtf(var + EPS);
        }
    }
    __syncthreads();

    xs[tid] = (v - s_mu) * s_inv * gamma[tid] + beta[tid];
    __syncthreads();

    // quarter-dots: thread computes sum over 64 elems for head h = tid&63
    {
        const int h = tid & 63;
        const int qq = tid >> 6;
        const float* wrow =
            ((h < 32) ? (w1 + h * SEQ_DIM) : (w2 + (h - 32) * SEQ_DIM)) + qq * 64;
        const float4* wp = (const float4*)wrow;
        const float4* xp = (const float4*)(xs + qq * 64);
        float a0 = 0.f, a1 = 0.f, a2 = 0.f, a3 = 0.f;
        #pragma unroll
        for (int k = 0; k < 16; k += 4) {
            const float4 w0 = wp[k + 0], x0 = xp[k + 0];
            const float4 w1v = wp[k + 1], x1 = xp[k + 1];
            const float4 w2v = wp[k + 2], x2 = xp[k + 2];
            const float4 w3v = wp[k + 3], x3 = xp[k + 3];
            a0 += w0.x * x0.x + w0.y * x0.y + w0.z * x0.z + w0.w * x0.w;
            a1 += w1v.x * x1.x + w1v.y * x1.y + w1v.z * x1.z + w1v.w * x1.w;
            a2 += w2v.x * x2.x + w2v.y * x2.y + w2v.z * x2.z + w2v.w * x2.w;
            a3 += w3v.x * x3.x + w3v.y * x3.y + w3v.z * x3.z + w3v.w * x3.w;
        }
        part[qq][h] = (a0 + a1) + (a2 + a3);
    }
    __syncthreads();

    if (tid < 64) {
        const float total = part[0][tid] + part[1][tid] + part[2][tid] + part[3][tid];
        if (tid < 32) {
            const float s1v = total + b1[tid];
            const __nv_bfloat16 hi = __float2bfloat16(s1v);
            const float lov = s1v - __bfloat162float(hi);
            g_s1b[i * 64 + tid]      = hi;
            g_s1b[i * 64 + 32 + tid] = __float2bfloat16(lov);
        } else {
            g_s2[i * HID + (tid - 32)] = total + b2[tid - 32];
        }
    }
}

// ---------------------------------------------------------------------------
// Kernel B: T[j][p][d] = sum_f s2[j][f] * w3[p*1024 + d*32 + f]
// written as bf16 hi/lo into g_Tb[j][p*64 + d] / [.. + 32 + d].
// ---------------------------------------------------------------------------
#define JT 8
__global__ void expand_t_kernel(const float* __restrict__ w3)
{
    const int jb = blockIdx.x;   // 0..47
    const int nq = blockIdx.y;   // 0..3
    const int tid = threadIdx.x; // 256

    __shared__ float s2s[JT][HID];
    s2s[tid >> 5][tid & 31] = g_s2[(jb * JT + (tid >> 5)) * HID + (tid & 31)];
    __syncthreads();

    float acc[4][JT];
    #pragma unroll
    for (int nn = 0; nn < 4; nn++)
        #pragma unroll
        for (int jj = 0; jj < JT; jj++) acc[nn][jj] = 0.f;

    #pragma unroll
    for (int nn = 0; nn < 4; nn++) {
        const int idx = nq * 1024 + nn * 256 + tid;
        const int d = idx & 31, p = idx >> 5;
        const float4* wp = (const float4*)(w3 + p * (HID * HID) + d * HID);
        #pragma unroll
        for (int q = 0; q < 8; q++) {
            const float4 w4 = wp[q];
            const int f = q * 4;
            #pragma unroll
            for (int jj = 0; jj < JT; jj++) {
                float a = acc[nn][jj];
                a += w4.x * s2s[jj][f + 0];
                a += w4.y * s2s[jj][f + 1];
                a += w4.z * s2s[jj][f + 2];
                a += w4.w * s2s[jj][f + 3];
                acc[nn][jj] = a;
            }
        }
    }

    #pragma unroll
    for (int jj = 0; jj < JT; jj++) {
        const int j = jb * JT + jj;
        #pragma unroll
        for (int nn = 0; nn < 4; nn++) {
            const int idx = nq * 1024 + nn * 256 + tid;
            const int d = idx & 31, p = idx >> 5;
            const float v = acc[nn][jj];
            const __nv_bfloat16 hi = __float2bfloat16(v);
            g_Tb[j * 8192 + p * 64 + d]      = hi;
            g_Tb[j * 8192 + p * 64 + 32 + d] = __float2bfloat16(v - __bfloat162float(hi));
        }
    }
}

// ---------------------------------------------------------------------------
// Kernel C: pair GEMM via mma.sync bf16 (hi/lo split, lo*lo dropped).
// Tile M=128 (i), N=128 (p) per (ib, j). 8 warps: 2x4, each 64x32.
// Smem rows padded to 72 bf16 (144B) -> conflict-free ldmatrix.
// ---------------------------------------------------------------------------
__global__ void __launch_bounds__(256) pair_mma_kernel(
    const float* __restrict__ b3, float* __restrict__ out)
{
    __shared__ __align__(16) __nv_bfloat16 As[128 * 72];
    __shared__ __align__(16) __nv_bfloat16 Bs[128 * 72];

    const int tid = threadIdx.x;
    const int wid = tid >> 5, lane = tid & 31;
    const int ib = blockIdx.x;  // 0..2
    const int j  = blockIdx.y;  // 0..383
    const int warp_m = wid >> 2;   // 0..1
    const int warp_n = wid & 3;    // 0..3

    // Fill smem tiles: 1024 x 16B each, coalesced.
    const uint4* ga = (const uint4*)(g_s1b + ib * 128 * 64);
    const uint4* gb = (const uint4*)(g_Tb + (size_t)j * 8192);
    #pragma unroll
    for (int q = 0; q < 4; q++) {
        const int idx = q * 256 + tid;          // 0..1023
        const int row = idx >> 3, c = idx & 7;  // 8x16B per 64-col row
        *(uint4*)(As + row * 72 + c * 8) = ga[idx];
        *(uint4*)(Bs + row * 72 + c * 8) = gb[idx];
    }
    __syncthreads();

    const uint32_t aBase = smem_to_u32(As);
    const uint32_t bBase = smem_to_u32(Bs);

    // ldmatrix lane addressing
    const int arow = warp_m * 64 + (lane & 15);
    const int acol = (lane >> 4) * 8;
    const uint32_t aAddr0 = aBase + (uint32_t)arow * 144 + (uint32_t)acol * 2;
    const int brow = warp_n * 32 + ((lane >> 4) & 1) * 8 + (lane & 7);
    const int bcol = ((lane >> 3) & 1) * 8;
    const uint32_t bAddr0 = bBase + (uint32_t)brow * 144 + (uint32_t)bcol * 2;

    // Accumulators init with bias
    float acc[4][4][4];
    const int pc = warp_n * 32 + 2 * (lane & 3);
    #pragma unroll
    for (int nt = 0; nt < 4; nt++) {
        const float bv0 = b3[pc + nt * 8];
        const float bv1 = b3[pc + nt * 8 + 1];
        #pragma unroll
        for (int mt = 0; mt < 4; mt++) {
            acc[mt][nt][0] = bv0; acc[mt][nt][1] = bv1;
            acc[mt][nt][2] = bv0; acc[mt][nt][3] = bv1;
        }
    }

    // 6 k16 steps: hi*hi (k 0,16), hi*lo (A 0,16 x B 32,48), lo*hi (A 32,48 x B 0,16)
    const int ka[6] = {0, 16, 0, 16, 32, 48};
    const int kb[6] = {0, 16, 32, 48, 0, 16};

    #pragma unroll
    for (int s = 0; s < 6; s++) {
        uint32_t af[4][4], bf[2][4];
        #pragma unroll
        for (int mt = 0; mt < 4; mt++)
            LDSM_X4(af[mt], aAddr0 + (uint32_t)(mt * 16 * 144 + ka[s] * 2));
        #pragma unroll
        for (int np = 0; np < 2; np++)
            LDSM_X4(bf[np], bAddr0 + (uint32_t)(np * 16 * 144 + kb[s] * 2));
        #pragma unroll
        for (int mt = 0; mt < 4; mt++)
            #pragma unroll
            for (int nt = 0; nt < 4; nt++)
                MMA16816(acc[mt][nt], af[mt],
                         bf[nt >> 1][(nt & 1) * 2], bf[nt >> 1][(nt & 1) * 2 + 1]);
    }

    // Epilogue: direct stores (bias already folded in)
    const int r0 = ib * 128 + warp_m * 64 + (lane >> 2);
    #pragma unroll
    for (int mt = 0; mt < 4; mt++) {
        const int i0 = r0 + mt * 16;
        float* p0 = out + ((size_t)i0 * LTOK + j) * PAIR_DIM + pc;
        float* p1 = p0 + (size_t)8 * LTOK * PAIR_DIM;
        #pragma unroll
        for (int nt = 0; nt < 4; nt++) {
            *(float2*)(p0 + nt * 8) = make_float2(acc[mt][nt][0], acc[mt][nt][1]);
            *(float2*)(p1 + nt * 8) = make_float2(acc[mt][nt][2], acc[mt][nt][3]);
        }
    }
}

// ---------------------------------------------------------------------------
extern "C" void kernel_launch(void* const* d_in, const int* in_sizes, int n_in,
                              void* d_out, int out_size)
{
    const float* seq   = (const float*)d_in[0];
    const float* gamma = (const float*)d_in[1];
    const float* beta  = (const float*)d_in[2];
    const float* w1    = (const float*)d_in[3];
    const float* b1    = (const float*)d_in[4];
    const float* w2    = (const float*)d_in[5];
    const float* b2    = (const float*)d_in[6];
    const float* w3    = (const float*)d_in[7];
    const float* b3    = (const float*)d_in[8];
    float* out = (float*)d_out;

    ln_proj_kernel<<<LTOK, 256>>>(seq, gamma, beta, w1, b1, w2, b2);
    expand_t_kernel<<<dim3(LTOK / JT, 4), 256>>>(w3);
    pair_mma_kernel<<<dim3(3, LTOK), 256>>>(b3, out);
}

// round 13
// speedup vs baseline: 1.3857x; 1.0422x over previous
#include <cuda_runtime.h>
#include <cuda_bf16.h>
#include <cstdint>

#define SEQ_DIM 256
#define PAIR_DIM 128
#define HID 32
#define LTOK 384
#define EPS 1e-5f

// Scratch (static device memory; no allocation)
__device__ float g_w12t[SEQ_DIM * 64];       // [k][h] h<32: w1 head h; h>=32: w2 head h-32
__device__ __nv_bfloat16 g_s1b[LTOK * 64];   // s1 split: [i][64], 0-31 hi, 32-63 lo
__device__ float g_s2[LTOK * HID];           // s2: [j][f]
__device__ __nv_bfloat16 g_Tb[LTOK * PAIR_DIM * 64]; // T split: [j][p][64], 0-31 hi(d), 32-63 lo(d)

// ---------------------------------------------------------------------------
__device__ __forceinline__ uint32_t smem_to_u32(const void* p) {
    uint32_t a;
    asm("{ .reg .u64 t; cvta.to.shared.u64 t, %1; cvt.u32.u64 %0, t; }"
        : "=r"(a) : "l"(p));
    return a;
}

#define LDSM_X4(r, addr) \
    asm volatile("ldmatrix.sync.aligned.m8n8.x4.shared.b16 {%0,%1,%2,%3}, [%4];" \
        : "=r"((r)[0]), "=r"((r)[1]), "=r"((r)[2]), "=r"((r)[3]) : "r"(addr))

#define MMA16816(c, a, b0, b1) \
    asm volatile("mma.sync.aligned.m16n8k16.row.col.f32.bf16.bf16.f32 " \
        "{%0,%1,%2,%3}, {%4,%5,%6,%7}, {%8,%9}, {%0,%1,%2,%3};" \
        : "+f"((c)[0]), "+f"((c)[1]), "+f"((c)[2]), "+f"((c)[3]) \
        : "r"((a)[0]), "r"((a)[1]), "r"((a)[2]), "r"((a)[3]), "r"(b0), "r"(b1))

// ---------------------------------------------------------------------------
// Kernel P: transpose w1/w2 into g_w12t[k*64 + h].
// ---------------------------------------------------------------------------
__global__ void __launch_bounds__(256) prep_wt_kernel(
    const float* __restrict__ w1, const float* __restrict__ w2)
{
    const int idx = blockIdx.x * 256 + threadIdx.x;  // 0..16383
    const int h = idx >> 8;          // 0..63
    const int k = idx & 255;         // coalesced read along k
    const float v = (h < 32) ? w1[h * SEQ_DIM + k] : w2[(h - 32) * SEQ_DIM + k];
    g_w12t[k * 64 + h] = v;
}

// ---------------------------------------------------------------------------
// Kernel A: LayerNorm + both projections. Block-per-token, 256 threads.
// Dot phase: warp w owns k-chunk [32w,32w+32), lane l owns heads 2l,2l+1.
// Weight loads fully coalesced (float2 x 32 lanes consecutive).
// ---------------------------------------------------------------------------
__global__ void __launch_bounds__(256) ln_proj_kernel(
    const float* __restrict__ seq,
    const float* __restrict__ gamma,
    const float* __restrict__ beta,
    const float* __restrict__ b1,
    const float* __restrict__ b2)
{
    const int i = blockIdx.x;
    const int tid = threadIdx.x;
    const int lane = tid & 31;
    const int wid = tid >> 5;

    __shared__ float xs[SEQ_DIM];
    __shared__ float2 red[8];
    __shared__ float s_mu, s_inv;
    __shared__ float part[8][64];

    const float v = seq[i * SEQ_DIM + tid];

    // one-pass sum + sumsq
    float s = v, q = v * v;
    #pragma unroll
    for (int o = 16; o > 0; o >>= 1) {
        s += __shfl_xor_sync(0xffffffffu, s, o);
        q += __shfl_xor_sync(0xffffffffu, q, o);
    }
    if (lane == 0) red[wid] = make_float2(s, q);
    __syncthreads();
    if (wid == 0) {
        float2 r = (lane < 8) ? red[lane] : make_float2(0.f, 0.f);
        #pragma unroll
        for (int o = 4; o > 0; o >>= 1) {
            r.x += __shfl_xor_sync(0xffffffffu, r.x, o);
            r.y += __shfl_xor_sync(0xffffffffu, r.y, o);
        }
        if (lane == 0) {
            const float mu = r.x * (1.0f / SEQ_DIM);
            const float var = r.y * (1.0f / SEQ_DIM) - mu * mu;
            s_mu = mu;
            s_inv = rsqrtf(var + EPS);
        }
    }
    __syncthreads();

    xs[tid] = (v - s_mu) * s_inv * gamma[tid] + beta[tid];
    __syncthreads();

    // coalesced dot: 32 k-steps of float2 per thread
    {
        float ax = 0.f, ay = 0.f;
        const float2* wp = (const float2*)(g_w12t + wid * 32 * 64) + lane;
        const float* xp = xs + wid * 32;
        #pragma unroll 8
        for (int kk = 0; kk < 32; kk++) {
            const float xv = xp[kk];
            const float2 wv = wp[kk * 32];
            ax += wv.x * xv;
            ay += wv.y * xv;
        }
        part[wid][2 * lane]     = ax;
        part[wid][2 * lane + 1] = ay;
    }
    __syncthreads();

    if (tid < 64) {
        float total = part[0][tid];
        #pragma unroll
        for (int qq = 1; qq < 8; qq++) total += part[qq][tid];
        if (tid < 32) {
            const float s1v = total + b1[tid];
            const __nv_bfloat16 hi = __float2bfloat16(s1v);
            const float lov = s1v - __bfloat162float(hi);
            g_s1b[i * 64 + tid]      = hi;
            g_s1b[i * 64 + 32 + tid] = __float2bfloat16(lov);
        } else {
            g_s2[i * HID + (tid - 32)] = total + b2[tid - 32];
        }
    }
}

// ---------------------------------------------------------------------------
// Kernel B: T[j][p][d] = sum_f s2[j][f] * w3[p*1024 + d*32 + f]
// bf16 hi/lo into g_Tb. Grid 48 x 8 (384 blocks), 2 (p,d) items per thread.
// ---------------------------------------------------------------------------
#define JT 8
__global__ void __launch_bounds__(256) expand_t_kernel(const float* __restrict__ w3)
{
    const int jb = blockIdx.x;   // 0..47
    const int nq = blockIdx.y;   // 0..7
    const int tid = threadIdx.x; // 256

    __shared__ float s2s[JT][HID];
    s2s[tid >> 5][tid & 31] = g_s2[(jb * JT + (tid >> 5)) * HID + (tid & 31)];
    __syncthreads();

    float acc[2][JT];
    #pragma unroll
    for (int nn = 0; nn < 2; nn++)
        #pragma unroll
        for (int jj = 0; jj < JT; jj++) acc[nn][jj] = 0.f;

    #pragma unroll
    for (int nn = 0; nn < 2; nn++) {
        const int idx = nq * 512 + nn * 256 + tid;
        const int d = idx & 31, p = idx >> 5;
        const float4* wp = (const float4*)(w3 + p * (HID * HID) + d * HID);
        #pragma unroll
        for (int q = 0; q < 8; q++) {
            const float4 w4 = wp[q];
            const int f = q * 4;
            #pragma unroll
            for (int jj = 0; jj < JT; jj++) {
                float a = acc[nn][jj];
                a += w4.x * s2s[jj][f + 0];
                a += w4.y * s2s[jj][f + 1];
                a += w4.z * s2s[jj][f + 2];
                a += w4.w * s2s[jj][f + 3];
                acc[nn][jj] = a;
            }
        }
    }

    #pragma unroll
    for (int jj = 0; jj < JT; jj++) {
        const int j = jb * JT + jj;
        #pragma unroll
        for (int nn = 0; nn < 2; nn++) {
            const int idx = nq * 512 + nn * 256 + tid;
            const int d = idx & 31, p = idx >> 5;
            const float v = acc[nn][jj];
            const __nv_bfloat16 hi = __float2bfloat16(v);
            g_Tb[j * 8192 + p * 64 + d]      = hi;
            g_Tb[j * 8192 + p * 64 + 32 + d] = __float2bfloat16(v - __bfloat162float(hi));
        }
    }
}

// ---------------------------------------------------------------------------
// Kernel C: pair GEMM via mma.sync bf16 (hi/lo split, lo*lo dropped).
// Tile M=128 (i), N=128 (p) per (ib, j). 8 warps: 2x4, each 64x32.
// Pass order grouped by A k-chunk so each A fragment is loaded once.
// ---------------------------------------------------------------------------
__global__ void __launch_bounds__(256) pair_mma_kernel(
    const float* __restrict__ b3, float* __restrict__ out)
{
    __shared__ __align__(16) __nv_bfloat16 As[128 * 72];
    __shared__ __align__(16) __nv_bfloat16 Bs[128 * 72];

    const int tid = threadIdx.x;
    const int wid = tid >> 5, lane = tid & 31;
    const int ib = blockIdx.x;  // 0..2
    const int j  = blockIdx.y;  // 0..383
    const int warp_m = wid >> 2;   // 0..1
    const int warp_n = wid & 3;    // 0..3

    // Fill smem tiles: 1024 x 16B each, coalesced.
    const uint4* ga = (const uint4*)(g_s1b + ib * 128 * 64);
    const uint4* gb = (const uint4*)(g_Tb + (size_t)j * 8192);
    #pragma unroll
    for (int q = 0; q < 4; q++) {
        const int idx = q * 256 + tid;          // 0..1023
        const int row = idx >> 3, c = idx & 7;  // 8x16B per 64-col row
        *(uint4*)(As + row * 72 + c * 8) = ga[idx];
        *(uint4*)(Bs + row * 72 + c * 8) = gb[idx];
    }
    __syncthreads();

    const uint32_t aBase = smem_to_u32(As);
    const uint32_t bBase = smem_to_u32(Bs);

    // ldmatrix lane addressing
    const int arow = warp_m * 64 + (lane & 15);
    const int acol = (lane >> 4) * 8;
    const uint32_t aAddr0 = aBase + (uint32_t)arow * 144 + (uint32_t)acol * 2;
    const int brow = warp_n * 32 + ((lane >> 4) & 1) * 8 + (lane & 7);
    const int bcol = ((lane >> 3) & 1) * 8;
    const uint32_t bAddr0 = bBase + (uint32_t)brow * 144 + (uint32_t)bcol * 2;

    // Accumulators init with bias
    float acc[4][4][4];
    const int pc = warp_n * 32 + 2 * (lane & 3);
    #pragma unroll
    for (int nt = 0; nt < 4; nt++) {
        const float bv0 = b3[pc + nt * 8];
        const float bv1 = b3[pc + nt * 8 + 1];
        #pragma unroll
        for (int mt = 0; mt < 4; mt++) {
            acc[mt][nt][0] = bv0; acc[mt][nt][1] = bv1;
            acc[mt][nt][2] = bv0; acc[mt][nt][3] = bv1;
        }
    }

    // Grouped passes: for each A k-chunk, list of B k-chunks.
    //  A k=0  (hi): B {0 (hi*hi), 32 (hi*lo)}
    //  A k=16 (hi): B {16 (hi*hi), 48 (hi*lo)}
    //  A k=32 (lo): B {0  (lo*hi)}
    //  A k=48 (lo): B {16 (lo*hi)}
    const int aks[4]   = {0, 16, 32, 48};
    const int bcnt[4]  = {2, 2, 1, 1};
    const int bks[4][2] = {{0, 32}, {16, 48}, {0, 0}, {16, 16}};

    #pragma unroll
    for (int g = 0; g < 4; g++) {
        uint32_t af[4][4];
        #pragma unroll
        for (int mt = 0; mt < 4; mt++)
            LDSM_X4(af[mt], aAddr0 + (uint32_t)(mt * 16 * 144 + aks[g] * 2));
        #pragma unroll
        for (int bi = 0; bi < 2; bi++) {
            if (bi >= bcnt[g]) break;
            uint32_t bf[2][4];
            #pragma unroll
            for (int np = 0; np < 2; np++)
                LDSM_X4(bf[np], bAddr0 + (uint32_t)(np * 16 * 144 + bks[g][bi] * 2));
            #pragma unroll
            for (int mt = 0; mt < 4; mt++)
                #pragma unroll
                for (int nt = 0; nt < 4; nt++)
                    MMA16816(acc[mt][nt], af[mt],
                             bf[nt >> 1][(nt & 1) * 2], bf[nt >> 1][(nt & 1) * 2 + 1]);
        }
    }

    // Epilogue: direct stores (bias already folded in)
    const int r0 = ib * 128 + warp_m * 64 + (lane >> 2);
    #pragma unroll
    for (int mt = 0; mt < 4; mt++) {
        const int i0 = r0 + mt * 16;
        float* p0 = out + ((size_t)i0 * LTOK + j) * PAIR_DIM + pc;
        float* p1 = p0 + (size_t)8 * LTOK * PAIR_DIM;
        #pragma unroll
        for (int nt = 0; nt < 4; nt++) {
            *(float2*)(p0 + nt * 8) = make_float2(acc[mt][nt][0], acc[mt][nt][1]);
            *(float2*)(p1 + nt * 8) = make_float2(acc[mt][nt][2], acc[mt][nt][3]);
        }
    }
}

// ---------------------------------------------------------------------------
extern "C" void kernel_launch(void* const* d_in, const int* in_sizes, int n_in,
                              void* d_out, int out_size)
{
    const float* seq   = (const float*)d_in[0];
    const float* gamma = (const float*)d_in[1];
    const float* beta  = (const float*)d_in[2];
    const float* w1    = (const float*)d_in[3];
    const float* b1    = (const float*)d_in[4];
    const float* w2    = (const float*)d_in[5];
    const float* b2    = (const float*)d_in[6];
    const float* w3    = (const float*)d_in[7];
    const float* b3    = (const float*)d_in[8];
    float* out = (float*)d_out;

    prep_wt_kernel<<<64, 256>>>(w1, w2);
    ln_proj_kernel<<<LTOK, 256>>>(seq, gamma, beta, b1, b2);
    expand_t_kernel<<<dim3(LTOK / JT, 8), 256>>>(w3);
    pair_mma_kernel<<<dim3(3, LTOK), 256>>>(b3, out);
}